// round 8
// baseline (speedup 1.0000x reference)
#include <cuda_runtime.h>

#define D_FEAT 64
#define N_ETYPES 8
#define EPS_V 1e-8f

// ---------------------------------------------------------------------------
// Single kernel, zero cross-block coordination.
//
// Layout: 4 threads per node, each thread owns 4 consecutive float4 chunks
// (front-batched loads, MLP_p1 = 4). 8 nodes per warp.
//
// Common path (node row nonzero — always, in practice):
//   4x LDG.128 -> nonzero test -> one warp ballot -> 4x STG.128. Nothing else.
//   Default cache policy so feat/out stay L2-resident across graph replays.
//
// Rare path (some node row is exactly all-zero): the OWNING WARP alone
// computes that node's full aggregation by scanning all E edges and
// recomputing per-source attention weights directly from feat. Slow but
// correct, fully self-contained — no data needed from other blocks.
// ---------------------------------------------------------------------------
__global__ void __launch_bounds__(256) k_aplayer(
    const float4* __restrict__ feat4,             // [N*16]
    const float4* __restrict__ attn4,             // [16]
    const float*  __restrict__ edge_weight,       // [T,T]
    const float*  __restrict__ edge_weight_param, // [T,1]
    const int*    __restrict__ src,
    const int*    __restrict__ dst,
    const int*    __restrict__ e_feat,
    float4*       __restrict__ out4,              // [N*16]
    int N, int E)
{
    const int tid  = blockIdx.x * blockDim.x + threadIdx.x;
    const int lane = threadIdx.x & 31;
    const int n    = tid >> 2;             // this thread's node
    const int q    = tid & 3;              // quarter of the node row
    const bool in_range = (n < N);

    float4 f0, f1, f2, f3;
    f0 = f1 = f2 = f3 = make_float4(0.f, 0.f, 0.f, 0.f);
    if (in_range) {
        const float4* p = feat4 + (size_t)n * 16 + q * 4;
        f0 = p[0]; f1 = p[1]; f2 = p[2]; f3 = p[3];   // front-batched, MLP=4
    }

    // Nonzero test over this thread's 16 values. (NaN != 0 -> nonzero;
    // -0.0 == 0 -> zero; same semantics as sum(|f|) == 0 in the reference.)
    const bool quarter_nz =
        (f0.x != 0.f) | (f0.y != 0.f) | (f0.z != 0.f) | (f0.w != 0.f) |
        (f1.x != 0.f) | (f1.y != 0.f) | (f1.z != 0.f) | (f1.w != 0.f) |
        (f2.x != 0.f) | (f2.y != 0.f) | (f2.z != 0.f) | (f2.w != 0.f) |
        (f3.x != 0.f) | (f3.y != 0.f) | (f3.z != 0.f) | (f3.w != 0.f);

    const unsigned bal = __ballot_sync(0xFFFFFFFFu, quarter_nz);

    // This thread's node is all-zero iff its 4-lane group contributed no bits.
    const int grp = lane >> 2;             // 0..7: node slot within the warp
    const bool my_node_zero = in_range && (((bal >> (grp * 4)) & 0xFu) == 0u);

    if (in_range && !my_node_zero) {
        float4* p = out4 + (size_t)n * 16 + q * 4;
        p[0] = f0; p[1] = f1; p[2] = f2; p[3] = f3;   // out == feat, bit-exact
    }

    // Warp-uniform: does this warp own any all-zero node?
    if (__ballot_sync(0xFFFFFFFFu, my_node_zero) == 0u)
        return;                                        // common path ends here

    // ======================= RARE PATH (warp-local) =======================
    // Per-edge-type weight table: lane t (t<8) holds ew[t].
    float my_ew = 0.f;
    if (lane < N_ETYPES) {
        float acc = 0.f;
        #pragma unroll
        for (int j = 0; j < N_ETYPES; ++j)
            acc += edge_weight[lane * N_ETYPES + j] * edge_weight_param[j];
        my_ew = acc + 1.0f;
    }

    // Attention chunk for lanes 0..15 (one float4 slot each).
    const int sub = lane & 15;
    const float4 a = __ldg(attn4 + sub);

    // First node owned by this warp.
    const int node_base = (blockIdx.x * blockDim.x + (threadIdx.x & ~31)) >> 2;

    #pragma unroll 1
    for (int h = 0; h < 8; ++h) {
        const int zn = node_base + h;
        const bool zn_zero = (((bal >> (h * 4)) & 0xFu) == 0u) && (zn < N);
        if (!zn_zero) continue;

        float4 acc   = make_float4(0.f, 0.f, 0.f, 0.f); // lanes 0..15: slot sub
        float  denom = 0.f;                              // replicated

        for (int e = lane; e < E; e += 32) {
            const bool match = (dst[e] == zn);
            unsigned m = __ballot_sync(0xFFFFFFFFu, match);
            while (m) {
                const int src_lane = __ffs(m) - 1;
                m &= m - 1;
                const int ee = (e - lane) + src_lane;    // matching edge id
                const int s  = src[ee];
                const int et = e_feat[ee];

                // Recompute w = exp(feat[s]·attn) * (feat[s] nonzero ? 1 : 0)
                float4 fs = make_float4(0.f, 0.f, 0.f, 0.f);
                if (lane < 16) fs = feat4[(size_t)s * 16 + sub];
                float s_abs = fabsf(fs.x) + fabsf(fs.y) + fabsf(fs.z) + fabsf(fs.w);
                float s_dot = fs.x * a.x + fs.y * a.y + fs.z * a.z + fs.w * a.w;
                #pragma unroll
                for (int off = 16; off > 0; off >>= 1) { // lanes 16..31 add 0
                    s_abs += __shfl_xor_sync(0xFFFFFFFFu, s_abs, off);
                    s_dot += __shfl_xor_sync(0xFFFFFFFFu, s_dot, off);
                }
                const float w = (s_abs == 0.f) ? 0.f : expf(s_dot); // T == 1
                denom += w;
                const float ew = __shfl_sync(0xFFFFFFFFu, my_ew, et - 1);
                const float sc = w * ew;
                if (lane < 16) {
                    acc.x += fs.x * sc; acc.y += fs.y * sc;
                    acc.z += fs.z * sc; acc.w += fs.w * sc;
                }
            }
        }

        const float dn  = (denom < EPS_V) ? 1.0f : denom;
        const float inv = 1.0f / dn;
        if (lane < 16) {
            out4[(size_t)zn * 16 + lane] =
                make_float4(acc.x * inv, acc.y * inv, acc.z * inv, acc.w * inv);
        }
    }
}

// ---------------------------------------------------------------------------
extern "C" void kernel_launch(void* const* d_in, const int* in_sizes, int n_in,
                              void* d_out, int out_size)
{
    const float* feat              = (const float*)d_in[0];
    const float* attn              = (const float*)d_in[1];
    const float* edge_weight       = (const float*)d_in[2];
    const float* edge_weight_param = (const float*)d_in[3];
    const int*   src               = (const int*)d_in[4];
    const int*   dst               = (const int*)d_in[5];
    const int*   e_feat            = (const int*)d_in[6];
    float*       out               = (float*)d_out;

    const int N = in_sizes[0] / D_FEAT;   // 100000
    const int E = in_sizes[4];            // 1000000

    const int threads = 256;              // 64 nodes per block (4 lanes/node)
    const int grid = (N * 4 + threads - 1) / threads;   // 1563

    k_aplayer<<<grid, threads>>>((const float4*)feat, (const float4*)attn,
                                 edge_weight, edge_weight_param,
                                 src, dst, e_feat,
                                 (float4*)out, N, E);
}

// round 9
// speedup vs baseline: 1.1628x; 1.1628x over previous
#include <cuda_runtime.h>

#define D_FEAT 64
#define N_ETYPES 8
#define EPS_V 1e-8f

// ---------------------------------------------------------------------------
// Single kernel, zero cross-block coordination.
//
// Layout: 16 lanes per node (one float4 per lane). Each thread processes
// 4 chunks spaced blockDim apart — every individual load/store is perfectly
// coalesced (warp = 512 contiguous bytes) AND the 4 loads are front-batched
// (MLP_p1 = 4) to hide DRAM latency. Block covers 64 nodes.
//
// Common path (all node rows nonzero — always, in practice):
//   4x coalesced LDG.128 -> 4 ballots -> 4x coalesced STG.128 -> 1 ballot.
//   Default cache policy so feat/out stay L2-resident across graph replays.
//
// Rare path (some node row exactly all-zero): the OWNING WARP alone computes
// that node's aggregation by scanning all E edges, recomputing per-source
// attention weights from feat. Slow but correct, fully self-contained.
// ---------------------------------------------------------------------------
__global__ void __launch_bounds__(256) k_aplayer(
    const float4* __restrict__ feat4,             // [N*16]
    const float4* __restrict__ attn4,             // [16]
    const float*  __restrict__ edge_weight,       // [T,T]
    const float*  __restrict__ edge_weight_param, // [T,1]
    const int*    __restrict__ src,
    const int*    __restrict__ dst,
    const int*    __restrict__ e_feat,
    float4*       __restrict__ out4,              // [N*16]
    int N, int E)
{
    const int lane   = threadIdx.x & 31;
    const int half   = lane >> 4;                  // node slot within chunk
    const int NCHUNK = N * 16;                     // total float4 chunks
    const int base   = blockIdx.x * (blockDim.x * 4) + threadIdx.x;

    float4 f[4];
    bool   inr[4];
    int    idx[4];
    #pragma unroll
    for (int k = 0; k < 4; ++k) {
        idx[k] = base + k * 256;
        inr[k] = (idx[k] < NCHUNK);
        f[k] = make_float4(0.f, 0.f, 0.f, 0.f);
        if (inr[k]) f[k] = feat4[idx[k]];          // front-batched, coalesced
    }

    // Per-chunk nonzero tests (NaN != 0 -> nonzero; -0.0 == 0 -> zero; same
    // semantics as sum(|row|) == 0 in the reference), then per-chunk ballots.
    unsigned bal[4];
    bool my_zero_any = false;                      // this thread's chunk is in
    #pragma unroll                                 // an in-range all-zero node
    for (int k = 0; k < 4; ++k) {
        const bool nz = (f[k].x != 0.f) | (f[k].y != 0.f) |
                        (f[k].z != 0.f) | (f[k].w != 0.f);
        bal[k] = __ballot_sync(0xFFFFFFFFu, nz);
        const bool node_zero = (((bal[k] >> (half * 16)) & 0xFFFFu) == 0u);
        if (inr[k]) {
            if (!node_zero) out4[idx[k]] = f[k];   // out == feat, bit-exact
            else            my_zero_any = true;
        }
    }

    // Warp-uniform rare-path trigger (in-range zero nodes only).
    if (__ballot_sync(0xFFFFFFFFu, my_zero_any) == 0u)
        return;                                    // common path ends here

    // ======================= RARE PATH (warp-local) =======================
    // Per-edge-type weight table: lane t (t<8) holds ew[t].
    float my_ew = 0.f;
    if (lane < N_ETYPES) {
        float acc = 0.f;
        #pragma unroll
        for (int j = 0; j < N_ETYPES; ++j)
            acc += edge_weight[lane * N_ETYPES + j] * edge_weight_param[j];
        my_ew = acc + 1.0f;
    }

    // Attention chunk for lanes 0..15 (one float4 slot each).
    const int sub = lane & 15;
    const float4 a = __ldg(attn4 + sub);

    // The warp's first chunk index for chunk-group k is
    //   blockIdx.x*1024 + k*256 + (threadIdx.x & ~31); it covers 2 nodes.
    const int warp_chunk0 = blockIdx.x * (blockDim.x * 4) + (threadIdx.x & ~31);

    #pragma unroll 1
    for (int k = 0; k < 4; ++k) {
        #pragma unroll 1
        for (int h = 0; h < 2; ++h) {
            const int zn = (warp_chunk0 + k * 256) / 16 + h;
            const bool zn_zero =
                (((bal[k] >> (h * 16)) & 0xFFFFu) == 0u) && (zn < N);
            if (!zn_zero) continue;

            float4 acc   = make_float4(0.f, 0.f, 0.f, 0.f);
            float  denom = 0.f;                    // replicated in all lanes

            for (int e = lane; e < E; e += 32) {
                const bool match = (dst[e] == zn);
                unsigned m = __ballot_sync(0xFFFFFFFFu, match);
                while (m) {
                    const int src_lane = __ffs(m) - 1;
                    m &= m - 1;
                    const int ee = (e - lane) + src_lane;
                    const int s  = src[ee];
                    const int et = e_feat[ee];

                    // w = exp(feat[s]·attn) * (feat[s] nonzero ? 1 : 0)
                    float4 fs = make_float4(0.f, 0.f, 0.f, 0.f);
                    if (lane < 16) fs = feat4[(size_t)s * 16 + sub];
                    float s_abs = fabsf(fs.x) + fabsf(fs.y)
                                + fabsf(fs.z) + fabsf(fs.w);
                    float s_dot = fs.x * a.x + fs.y * a.y
                                + fs.z * a.z + fs.w * a.w;
                    #pragma unroll
                    for (int off = 16; off > 0; off >>= 1) {
                        s_abs += __shfl_xor_sync(0xFFFFFFFFu, s_abs, off);
                        s_dot += __shfl_xor_sync(0xFFFFFFFFu, s_dot, off);
                    }
                    const float w = (s_abs == 0.f) ? 0.f : expf(s_dot);
                    denom += w;
                    const float ew = __shfl_sync(0xFFFFFFFFu, my_ew, et - 1);
                    const float sc = w * ew;
                    if (lane < 16) {
                        acc.x += fs.x * sc; acc.y += fs.y * sc;
                        acc.z += fs.z * sc; acc.w += fs.w * sc;
                    }
                }
            }

            const float dn  = (denom < EPS_V) ? 1.0f : denom;
            const float inv = 1.0f / dn;
            if (lane < 16) {
                out4[(size_t)zn * 16 + lane] = make_float4(
                    acc.x * inv, acc.y * inv, acc.z * inv, acc.w * inv);
            }
        }
    }
}

// ---------------------------------------------------------------------------
extern "C" void kernel_launch(void* const* d_in, const int* in_sizes, int n_in,
                              void* d_out, int out_size)
{
    const float* feat              = (const float*)d_in[0];
    const float* attn              = (const float*)d_in[1];
    const float* edge_weight       = (const float*)d_in[2];
    const float* edge_weight_param = (const float*)d_in[3];
    const int*   src               = (const int*)d_in[4];
    const int*   dst               = (const int*)d_in[5];
    const int*   e_feat            = (const int*)d_in[6];
    float*       out               = (float*)d_out;

    const int N = in_sizes[0] / D_FEAT;   // 100000
    const int E = in_sizes[4];            // 1000000

    const int threads = 256;
    const int chunks_per_block = threads * 4;            // 1024 float4s
    const int grid = (N * 16 + chunks_per_block - 1) / chunks_per_block; // 1563

    k_aplayer<<<grid, threads>>>((const float4*)feat, (const float4*)attn,
                                 edge_weight, edge_weight_param,
                                 src, dst, e_feat,
                                 (float4*)out, N, E);
}

// round 10
// speedup vs baseline: 1.1662x; 1.0029x over previous
#include <cuda_runtime.h>

#define D_FEAT 64
#define N_ETYPES 8
#define EPS_V 1e-8f
#define CHUNKS 8

// ---------------------------------------------------------------------------
// Single kernel, zero cross-block coordination.
//
// Layout: 16 lanes per node (one float4 per lane). Each thread processes
// 8 chunks spaced blockDim apart — every load/store is perfectly coalesced
// (warp = 512 contiguous bytes) and the 8 loads are front-batched
// (MLP_p1 = 8). Grid = 782 blocks -> ~1 wave at 5 blocks/SM residency.
//
// Common path (all node rows nonzero — always, in practice):
//   8x coalesced LDG.128 -> 8 ballots -> 8x coalesced STG.128 -> 1 ballot.
//   Default cache policy so feat/out stay L2-resident across graph replays.
//
// Rare path (some node row exactly all-zero): the OWNING WARP alone computes
// that node's aggregation by scanning all E edges, recomputing per-source
// attention weights from feat. Slow but correct, fully self-contained.
// ---------------------------------------------------------------------------
__global__ void __launch_bounds__(256, 5) k_aplayer(
    const float4* __restrict__ feat4,             // [N*16]
    const float4* __restrict__ attn4,             // [16]
    const float*  __restrict__ edge_weight,       // [T,T]
    const float*  __restrict__ edge_weight_param, // [T,1]
    const int*    __restrict__ src,
    const int*    __restrict__ dst,
    const int*    __restrict__ e_feat,
    float4*       __restrict__ out4,              // [N*16]
    int N, int E)
{
    const int lane   = threadIdx.x & 31;
    const int half   = lane >> 4;                  // node slot within chunk
    const int NCHUNK = N * 16;                     // total float4 chunks
    const int base   = blockIdx.x * (blockDim.x * CHUNKS) + threadIdx.x;

    float4 f[CHUNKS];
    #pragma unroll
    for (int k = 0; k < CHUNKS; ++k) {             // front-batched, coalesced
        const int idx = base + k * 256;
        f[k] = make_float4(0.f, 0.f, 0.f, 0.f);
        if (idx < NCHUNK) f[k] = feat4[idx];
    }

    // Per-chunk nonzero tests (NaN != 0 -> nonzero; -0.0 == 0 -> zero; same
    // semantics as sum(|row|) == 0 in the reference), then per-chunk ballots.
    unsigned bal[CHUNKS];
    bool my_zero_any = false;          // this thread's chunk is in an
    #pragma unroll                     // in-range all-zero node
    for (int k = 0; k < CHUNKS; ++k) {
        const bool nz = (f[k].x != 0.f) | (f[k].y != 0.f) |
                        (f[k].z != 0.f) | (f[k].w != 0.f);
        bal[k] = __ballot_sync(0xFFFFFFFFu, nz);
        const bool node_zero = (((bal[k] >> (half * 16)) & 0xFFFFu) == 0u);
        const int idx = base + k * 256;
        if (idx < NCHUNK) {
            if (!node_zero) out4[idx] = f[k];      // out == feat, bit-exact
            else            my_zero_any = true;
        }
    }

    // Warp-uniform rare-path trigger (in-range zero nodes only).
    if (__ballot_sync(0xFFFFFFFFu, my_zero_any) == 0u)
        return;                                    // common path ends here

    // ======================= RARE PATH (warp-local) =======================
    // Per-edge-type weight table: lane t (t<8) holds ew[t].
    float my_ew = 0.f;
    if (lane < N_ETYPES) {
        float acc = 0.f;
        #pragma unroll
        for (int j = 0; j < N_ETYPES; ++j)
            acc += edge_weight[lane * N_ETYPES + j] * edge_weight_param[j];
        my_ew = acc + 1.0f;
    }

    // Attention chunk for lanes 0..15 (one float4 slot each).
    const int sub = lane & 15;
    const float4 a = __ldg(attn4 + sub);

    // The warp's first chunk for group k is base_warp + k*256; 2 nodes each.
    const int warp_chunk0 =
        blockIdx.x * (blockDim.x * CHUNKS) + (threadIdx.x & ~31);

    #pragma unroll 1
    for (int k = 0; k < CHUNKS; ++k) {
        #pragma unroll 1
        for (int h = 0; h < 2; ++h) {
            const int zn = (warp_chunk0 + k * 256) / 16 + h;
            const bool zn_zero =
                (((bal[k] >> (h * 16)) & 0xFFFFu) == 0u) && (zn < N);
            if (!zn_zero) continue;

            float4 acc   = make_float4(0.f, 0.f, 0.f, 0.f);
            float  denom = 0.f;                    // replicated in all lanes

            for (int e = lane; e < E; e += 32) {
                const bool match = (dst[e] == zn);
                unsigned m = __ballot_sync(0xFFFFFFFFu, match);
                while (m) {
                    const int src_lane = __ffs(m) - 1;
                    m &= m - 1;
                    const int ee = (e - lane) + src_lane;
                    const int s  = src[ee];
                    const int et = e_feat[ee];

                    // w = exp(feat[s]·attn) * (feat[s] nonzero ? 1 : 0)
                    float4 fs = make_float4(0.f, 0.f, 0.f, 0.f);
                    if (lane < 16) fs = feat4[(size_t)s * 16 + sub];
                    float s_abs = fabsf(fs.x) + fabsf(fs.y)
                                + fabsf(fs.z) + fabsf(fs.w);
                    float s_dot = fs.x * a.x + fs.y * a.y
                                + fs.z * a.z + fs.w * a.w;
                    #pragma unroll
                    for (int off = 16; off > 0; off >>= 1) {
                        s_abs += __shfl_xor_sync(0xFFFFFFFFu, s_abs, off);
                        s_dot += __shfl_xor_sync(0xFFFFFFFFu, s_dot, off);
                    }
                    const float w = (s_abs == 0.f) ? 0.f : expf(s_dot);
                    denom += w;
                    const float ew = __shfl_sync(0xFFFFFFFFu, my_ew, et - 1);
                    const float sc = w * ew;
                    if (lane < 16) {
                        acc.x += fs.x * sc; acc.y += fs.y * sc;
                        acc.z += fs.z * sc; acc.w += fs.w * sc;
                    }
                }
            }

            const float dn  = (denom < EPS_V) ? 1.0f : denom;
            const float inv = 1.0f / dn;
            if (lane < 16) {
                out4[(size_t)zn * 16 + lane] = make_float4(
                    acc.x * inv, acc.y * inv, acc.z * inv, acc.w * inv);
            }
        }
    }
}

// ---------------------------------------------------------------------------
extern "C" void kernel_launch(void* const* d_in, const int* in_sizes, int n_in,
                              void* d_out, int out_size)
{
    const float* feat              = (const float*)d_in[0];
    const float* attn              = (const float*)d_in[1];
    const float* edge_weight       = (const float*)d_in[2];
    const float* edge_weight_param = (const float*)d_in[3];
    const int*   src               = (const int*)d_in[4];
    const int*   dst               = (const int*)d_in[5];
    const int*   e_feat            = (const int*)d_in[6];
    float*       out               = (float*)d_out;

    const int N = in_sizes[0] / D_FEAT;   // 100000
    const int E = in_sizes[4];            // 1000000

    const int threads = 256;
    const int chunks_per_block = threads * CHUNKS;        // 2048 float4s
    const int grid = (N * 16 + chunks_per_block - 1) / chunks_per_block; // 782

    k_aplayer<<<grid, threads>>>((const float4*)feat, (const float4*)attn,
                                 edge_weight, edge_weight_param,
                                 src, dst, e_feat,
                                 (float4*)out, N, E);
}

// round 11
// speedup vs baseline: 1.1976x; 1.0269x over previous
#include <cuda_runtime.h>

#define D_FEAT 64
#define N_ETYPES 8
#define EPS_V 1e-8f
#define CHUNKS 8

// ---------------------------------------------------------------------------
// Single kernel, zero cross-block coordination.
//
// Identical to the R9 kernel except ONE variable: output stores use __stwt
// (write-through, no L2 dirty-line accumulation). Hypothesis: per-replay
// dirty writebacks were evicting/contending with the feat read stream in L2;
// routing writes around L2 lets feat stay L2-resident across graph replays.
//
// Layout: 16 lanes per node (one float4 per lane). Each thread processes
// 8 chunks spaced blockDim apart — coalesced (warp = 512 contiguous bytes)
// and front-batched (MLP_p1 = 8).
//
// Rare path (some node row exactly all-zero): the OWNING WARP alone computes
// that node's aggregation by scanning all E edges. Slow but correct,
// fully self-contained.
// ---------------------------------------------------------------------------
__global__ void __launch_bounds__(256, 5) k_aplayer(
    const float4* __restrict__ feat4,             // [N*16]
    const float4* __restrict__ attn4,             // [16]
    const float*  __restrict__ edge_weight,       // [T,T]
    const float*  __restrict__ edge_weight_param, // [T,1]
    const int*    __restrict__ src,
    const int*    __restrict__ dst,
    const int*    __restrict__ e_feat,
    float4*       __restrict__ out4,              // [N*16]
    int N, int E)
{
    const int lane   = threadIdx.x & 31;
    const int half   = lane >> 4;                  // node slot within chunk
    const int NCHUNK = N * 16;                     // total float4 chunks
    const int base   = blockIdx.x * (blockDim.x * CHUNKS) + threadIdx.x;

    float4 f[CHUNKS];
    #pragma unroll
    for (int k = 0; k < CHUNKS; ++k) {             // front-batched, coalesced
        const int idx = base + k * 256;
        f[k] = make_float4(0.f, 0.f, 0.f, 0.f);
        if (idx < NCHUNK) f[k] = feat4[idx];
    }

    // Per-chunk nonzero tests (NaN != 0 -> nonzero; -0.0 == 0 -> zero; same
    // semantics as sum(|row|) == 0 in the reference), then per-chunk ballots.
    unsigned bal[CHUNKS];
    bool my_zero_any = false;          // this thread's chunk is in an
    #pragma unroll                     // in-range all-zero node
    for (int k = 0; k < CHUNKS; ++k) {
        const bool nz = (f[k].x != 0.f) | (f[k].y != 0.f) |
                        (f[k].z != 0.f) | (f[k].w != 0.f);
        bal[k] = __ballot_sync(0xFFFFFFFFu, nz);
        const bool node_zero = (((bal[k] >> (half * 16)) & 0xFFFFu) == 0u);
        const int idx = base + k * 256;
        if (idx < NCHUNK) {
            if (!node_zero) __stwt(out4 + idx, f[k]);  // WT: bypass L2 reuse
            else            my_zero_any = true;
        }
    }

    // Warp-uniform rare-path trigger (in-range zero nodes only).
    if (__ballot_sync(0xFFFFFFFFu, my_zero_any) == 0u)
        return;                                    // common path ends here

    // ======================= RARE PATH (warp-local) =======================
    // Per-edge-type weight table: lane t (t<8) holds ew[t].
    float my_ew = 0.f;
    if (lane < N_ETYPES) {
        float acc = 0.f;
        #pragma unroll
        for (int j = 0; j < N_ETYPES; ++j)
            acc += edge_weight[lane * N_ETYPES + j] * edge_weight_param[j];
        my_ew = acc + 1.0f;
    }

    // Attention chunk for lanes 0..15 (one float4 slot each).
    const int sub = lane & 15;
    const float4 a = __ldg(attn4 + sub);

    // The warp's first chunk for group k is base_warp + k*256; 2 nodes each.
    const int warp_chunk0 =
        blockIdx.x * (blockDim.x * CHUNKS) + (threadIdx.x & ~31);

    #pragma unroll 1
    for (int k = 0; k < CHUNKS; ++k) {
        #pragma unroll 1
        for (int h = 0; h < 2; ++h) {
            const int zn = (warp_chunk0 + k * 256) / 16 + h;
            const bool zn_zero =
                (((bal[k] >> (h * 16)) & 0xFFFFu) == 0u) && (zn < N);
            if (!zn_zero) continue;

            float4 acc   = make_float4(0.f, 0.f, 0.f, 0.f);
            float  denom = 0.f;                    // replicated in all lanes

            for (int e = lane; e < E; e += 32) {
                const bool match = (dst[e] == zn);
                unsigned m = __ballot_sync(0xFFFFFFFFu, match);
                while (m) {
                    const int src_lane = __ffs(m) - 1;
                    m &= m - 1;
                    const int ee = (e - lane) + src_lane;
                    const int s  = src[ee];
                    const int et = e_feat[ee];

                    // w = exp(feat[s]·attn) * (feat[s] nonzero ? 1 : 0)
                    float4 fs = make_float4(0.f, 0.f, 0.f, 0.f);
                    if (lane < 16) fs = feat4[(size_t)s * 16 + sub];
                    float s_abs = fabsf(fs.x) + fabsf(fs.y)
                                + fabsf(fs.z) + fabsf(fs.w);
                    float s_dot = fs.x * a.x + fs.y * a.y
                                + fs.z * a.z + fs.w * a.w;
                    #pragma unroll
                    for (int off = 16; off > 0; off >>= 1) {
                        s_abs += __shfl_xor_sync(0xFFFFFFFFu, s_abs, off);
                        s_dot += __shfl_xor_sync(0xFFFFFFFFu, s_dot, off);
                    }
                    const float w = (s_abs == 0.f) ? 0.f : expf(s_dot);
                    denom += w;
                    const float ew = __shfl_sync(0xFFFFFFFFu, my_ew, et - 1);
                    const float sc = w * ew;
                    if (lane < 16) {
                        acc.x += fs.x * sc; acc.y += fs.y * sc;
                        acc.z += fs.z * sc; acc.w += fs.w * sc;
                    }
                }
            }

            const float dn  = (denom < EPS_V) ? 1.0f : denom;
            const float inv = 1.0f / dn;
            if (lane < 16) {
                out4[(size_t)zn * 16 + lane] = make_float4(
                    acc.x * inv, acc.y * inv, acc.z * inv, acc.w * inv);
            }
        }
    }
}

// ---------------------------------------------------------------------------
extern "C" void kernel_launch(void* const* d_in, const int* in_sizes, int n_in,
                              void* d_out, int out_size)
{
    const float* feat              = (const float*)d_in[0];
    const float* attn              = (const float*)d_in[1];
    const float* edge_weight       = (const float*)d_in[2];
    const float* edge_weight_param = (const float*)d_in[3];
    const int*   src               = (const int*)d_in[4];
    const int*   dst               = (const int*)d_in[5];
    const int*   e_feat            = (const int*)d_in[6];
    float*       out               = (float*)d_out;

    const int N = in_sizes[0] / D_FEAT;   // 100000
    const int E = in_sizes[4];            // 1000000

    const int threads = 256;
    const int chunks_per_block = threads * CHUNKS;        // 2048 float4s
    const int grid = (N * 16 + chunks_per_block - 1) / chunks_per_block; // 782

    k_aplayer<<<grid, threads>>>((const float4*)feat, (const float4*)attn,
                                 edge_weight, edge_weight_param,
                                 src, dst, e_feat,
                                 (float4*)out, N, E);
}